// round 9
// baseline (speedup 1.0000x reference)
#include <cuda_runtime.h>
#include <cuda_fp16.h>
#include <cstdint>

#define NN   12288
#define KK   32
#define DD   128

typedef unsigned long long ull;

// Scratch: G = raw_features @ W_lin^T, fp16 (N x 128, 3.15 MB)
__device__ __align__(16) __half g_Gh[NN * DD];
// Scratch: masked gather weights w[b][k] (1.5 MB)
__device__ __align__(16) float  g_w[NN * KK];

// ---------------------------------------------------------------------------
// packed f32x2 helpers
// ---------------------------------------------------------------------------
__device__ __forceinline__ ull pack_dup(float x) {
    ull r;
    asm("mov.b64 %0, {%1, %1};" : "=l"(r) : "f"(x));
    return r;
}
__device__ __forceinline__ void fma2(ull& d, ull a, ull b) {
    asm("fma.rn.f32x2 %0, %1, %2, %0;" : "+l"(d) : "l"(a), "l"(b));
}
__device__ __forceinline__ void unpack2(float& lo, float& hi, ull v) {
    asm("mov.b64 {%0, %1}, %2;" : "=f"(lo), "=f"(hi) : "l"(v));
}

// ---------------------------------------------------------------------------
// Kernel 1 (combined): 768 blocks x 128 threads.
//   odd  blocks: w-prep — g_w[e] = (nb==node) ? 0 : rew[node][nb]
//                (pure random-DRAM latency work, negligible issue usage)
//   even blocks: GEMM G = F @ W^T (fp16 out), 64x64 tile, FFMA2 microtile
// Parity interleave => both kinds co-resident; wprep hides in GEMM stalls.
// ---------------------------------------------------------------------------
__global__ void __launch_bounds__(128, 3)
gemm_wprep_kernel(const float* __restrict__ F, const float* __restrict__ W,
                  const int* __restrict__ nodes,
                  const int* __restrict__ neighbors,
                  const float* __restrict__ rew)
{
    const int tid = threadIdx.x;
    const int bid = blockIdx.x;
    const int gid = bid >> 1;

    if (bid & 1) {
        // ---------------- w-prep block: 1024 entries, batched MLP ----------
        const int base = gid * 1024 + tid;
        int   nd8[8], nb8[8];
        #pragma unroll
        for (int i = 0; i < 8; i++) {
            const int e = base + i * 128;
            nd8[i] = __ldg(&nodes[e >> 5]);        // L1/L2-resident
            nb8[i] = __ldg(&neighbors[e]);         // coalesced
        }
        float w8[8];
        #pragma unroll
        for (int i = 0; i < 8; i++) {
            float w = 0.0f;
            if (nb8[i] != nd8[i])
                w = __ldg(&rew[(size_t)nd8[i] * NN + nb8[i]]);  // random DRAM
            w8[i] = w;
        }
        #pragma unroll
        for (int i = 0; i < 8; i++)
            g_w[base + i * 128] = w8[i];           // coalesced store
        return;
    }

    // -------------------- GEMM block (gid in [0, 384)) ----------------------
    extern __shared__ float sm[];
    float* Fst = sm;                 // 128 * 66  (Fst[k*66 + m])
    float* Wt  = sm + 128 * 66;      // 128 * 66  (Wt [k*66 + n])

    const int bm = gid % 192;        // row tile
    const int bn = gid / 192;        // col tile

    const float* Fblk = F + (size_t)bm * 64 * DD;
    const float* Wblk = W + (size_t)bn * 64 * DD;

    #pragma unroll 8
    for (int idx = tid; idx < 64 * 128; idx += 128) {
        int r = idx >> 7, k = idx & 127;
        Fst[k * 66 + r] = Fblk[idx];
        Wt [k * 66 + r] = Wblk[idx];
    }
    __syncthreads();

    const int tx = tid & 15;   // cols 4*tx .. 4*tx+3
    const int ty = tid >> 4;   // rows 8*ty .. 8*ty+7

    ull acc[4][4];
    #pragma unroll
    for (int p = 0; p < 4; p++)
        #pragma unroll
        for (int c = 0; c < 4; c++)
            acc[p][c] = 0ULL;

    #pragma unroll 4
    for (int kk = 0; kk < 128; kk++) {
        const float* fr = &Fst[kk * 66 + 8 * ty];
        ull a2[4];
        #pragma unroll
        for (int p = 0; p < 4; p++)
            a2[p] = *reinterpret_cast<const ull*>(&fr[2 * p]);

        float2 b01 = *reinterpret_cast<const float2*>(&Wt[kk * 66 + 4 * tx]);
        float2 b23 = *reinterpret_cast<const float2*>(&Wt[kk * 66 + 4 * tx + 2]);
        ull bd[4];
        bd[0] = pack_dup(b01.x); bd[1] = pack_dup(b01.y);
        bd[2] = pack_dup(b23.x); bd[3] = pack_dup(b23.y);

        #pragma unroll
        for (int p = 0; p < 4; p++)
            #pragma unroll
            for (int c = 0; c < 4; c++)
                fma2(acc[p][c], a2[p], bd[c]);
    }

    float v[8][4];
    #pragma unroll
    for (int p = 0; p < 4; p++)
        #pragma unroll
        for (int c = 0; c < 4; c++) {
            float lo, hi;
            unpack2(lo, hi, acc[p][c]);
            v[2 * p][c]     = lo;
            v[2 * p + 1][c] = hi;
        }

    const int gm0 = bm * 64 + 8 * ty;
    const int gn0 = bn * 64 + 4 * tx;
    #pragma unroll
    for (int r = 0; r < 8; r++) {
        __half2 h01 = __floats2half2_rn(v[r][0], v[r][1]);
        __half2 h23 = __floats2half2_rn(v[r][2], v[r][3]);
        uint2 st;
        st.x = *reinterpret_cast<unsigned*>(&h01);
        st.y = *reinterpret_cast<unsigned*>(&h23);
        *reinterpret_cast<uint2*>(&g_Gh[(size_t)(gm0 + r) * DD + gn0]) = st;
    }
}

// ---------------------------------------------------------------------------
// Kernel 2: out[b][d] = relu( sum_k w[b][k] * G[nb[b][k]][d] + bias[d] )
// (R7-measured 12.7us version.) 256 thr = 16 nodes/block; warp handles 2
// nodes (lanes 0-15 / 16-31), lane owns 8 fp16 cols (one LDG.128 per k).
// w precomputed in g_w (coalesced). k unrolled by 4. fp32 accumulate.
// ---------------------------------------------------------------------------
__global__ void __launch_bounds__(256)
gather_kernel(const int* __restrict__ neighbors,
              const float* __restrict__ b_lin,
              float* __restrict__ out)
{
    __shared__ int   nb_s[16][KK];
    __shared__ float w_s [16][KK];

    const int tid = threadIdx.x;
    const int b0  = blockIdx.x * 16;

    #pragma unroll
    for (int i = 0; i < 2; i++) {
        const int e  = tid + i * 256;
        const int ln = e >> 5;
        const int k  = e & 31;
        const int gi = (b0 + ln) * KK + k;
        nb_s[ln][k] = neighbors[gi];
        w_s [ln][k] = g_w[gi];
    }
    __syncthreads();

    const int lane = tid & 31;
    const int ln2  = ((tid >> 5) << 1) | (lane >> 4);  // local node 0..15
    const int col  = (lane & 15) * 8;                  // 8 cols per lane
    const int b    = b0 + ln2;

    float acc[8];
    #pragma unroll
    for (int i = 0; i < 8; i++) acc[i] = 0.0f;

    #pragma unroll
    for (int kb = 0; kb < KK; kb += 4) {
        uint4 g[4];
        float wv[4];
        #pragma unroll
        for (int u = 0; u < 4; u++) {
            const int nb = nb_s[ln2][kb + u];
            wv[u] = w_s[ln2][kb + u];
            g[u]  = __ldg(reinterpret_cast<const uint4*>(
                              &g_Gh[(size_t)nb * DD + col]));
        }
        #pragma unroll
        for (int u = 0; u < 4; u++) {
            float2 f0 = __half22float2(*reinterpret_cast<__half2*>(&g[u].x));
            float2 f1 = __half22float2(*reinterpret_cast<__half2*>(&g[u].y));
            float2 f2 = __half22float2(*reinterpret_cast<__half2*>(&g[u].z));
            float2 f3 = __half22float2(*reinterpret_cast<__half2*>(&g[u].w));
            acc[0] = fmaf(wv[u], f0.x, acc[0]);
            acc[1] = fmaf(wv[u], f0.y, acc[1]);
            acc[2] = fmaf(wv[u], f1.x, acc[2]);
            acc[3] = fmaf(wv[u], f1.y, acc[3]);
            acc[4] = fmaf(wv[u], f2.x, acc[4]);
            acc[5] = fmaf(wv[u], f2.y, acc[5]);
            acc[6] = fmaf(wv[u], f3.x, acc[6]);
            acc[7] = fmaf(wv[u], f3.y, acc[7]);
        }
    }

    const float4 bias0 = __ldg(reinterpret_cast<const float4*>(&b_lin[col]));
    const float4 bias1 = __ldg(reinterpret_cast<const float4*>(&b_lin[col + 4]));
    float4 o0, o1;
    o0.x = fmaxf(acc[0] + bias0.x, 0.f);
    o0.y = fmaxf(acc[1] + bias0.y, 0.f);
    o0.z = fmaxf(acc[2] + bias0.z, 0.f);
    o0.w = fmaxf(acc[3] + bias0.w, 0.f);
    o1.x = fmaxf(acc[4] + bias1.x, 0.f);
    o1.y = fmaxf(acc[5] + bias1.y, 0.f);
    o1.z = fmaxf(acc[6] + bias1.z, 0.f);
    o1.w = fmaxf(acc[7] + bias1.w, 0.f);
    float* op = &out[(size_t)b * DD + col];
    *reinterpret_cast<float4*>(op)     = o0;
    *reinterpret_cast<float4*>(op + 4) = o1;
}

// ---------------------------------------------------------------------------
// Launch. Inputs: nodes(i32 N), neighbors(i32 N*K), raw_features(f32 N*128),
//                 reweighted(f32 N*N), W_lin(f32 128*128), b_lin(f32 128)
// ---------------------------------------------------------------------------
extern "C" void kernel_launch(void* const* d_in, const int* in_sizes, int n_in,
                              void* d_out, int out_size)
{
    const int*   nodes      = (const int*)  d_in[0];
    const int*   neighbors  = (const int*)  d_in[1];
    const float* raw_feats  = (const float*)d_in[2];
    const float* reweighted = (const float*)d_in[3];
    const float* W_lin      = (const float*)d_in[4];
    const float* b_lin      = (const float*)d_in[5];
    float*       out        = (float*)d_out;

    const int smem = 2 * 128 * 66 * (int)sizeof(float);  // 67584 B
    static bool attr_set = false;
    if (!attr_set) {
        cudaFuncSetAttribute(gemm_wprep_kernel,
                             cudaFuncAttributeMaxDynamicSharedMemorySize, smem);
        attr_set = true;
    }

    gemm_wprep_kernel<<<768, 128, smem>>>(raw_feats, W_lin,
                                          nodes, neighbors, reweighted);
    gather_kernel<<<NN / 16, 256>>>(neighbors, b_lin, out);
}

// round 10
// speedup vs baseline: 1.1404x; 1.1404x over previous
#include <cuda_runtime.h>
#include <cuda_fp16.h>
#include <cstdint>

#define NN   12288
#define KK   32
#define DD   128

typedef unsigned long long ull;

// Scratch: G = raw_features @ W_lin^T, fp16 (N x 128, 3.15 MB)
__device__ __align__(16) __half g_Gh[NN * DD];
// Scratch: masked gather weights w[b][k] (1.5 MB)
__device__ __align__(16) float  g_w[NN * KK];

// ---------------------------------------------------------------------------
// packed f32x2 helpers
// ---------------------------------------------------------------------------
__device__ __forceinline__ ull pack_dup(float x) {
    ull r;
    asm("mov.b64 %0, {%1, %1};" : "=l"(r) : "f"(x));
    return r;
}
__device__ __forceinline__ void fma2(ull& d, ull a, ull b) {
    asm("fma.rn.f32x2 %0, %1, %2, %0;" : "+l"(d) : "l"(a), "l"(b));
}
__device__ __forceinline__ void unpack2(float& lo, float& hi, ull v) {
    asm("mov.b64 {%0, %1}, %2;" : "=f"(lo), "=f"(hi) : "l"(v));
}

// ---------------------------------------------------------------------------
// Kernel 0: w-prep with MAXIMAL TLP. 1536 blocks x 256 thr, 1 entry/thread.
// ~64 resident warps/SM, 32 independent random sectors in flight per warp
// -> the 393K random rew loads are latency-hidden; DRAM floor ~1.6us.
// ---------------------------------------------------------------------------
__global__ void __launch_bounds__(256)
wprep_kernel(const int* __restrict__ nodes,
             const int* __restrict__ neighbors,
             const float* __restrict__ rew)
{
    const int e    = blockIdx.x * 256 + threadIdx.x;   // entry = b*32 + k
    const int node = __ldg(&nodes[e >> 5]);            // broadcast in warp
    const int nb   = __ldg(&neighbors[e]);             // coalesced
    float w = 0.0f;
    if (nb != node)
        w = __ldg(&rew[(size_t)node * NN + nb]);       // random 32B sector
    g_w[e] = w;                                        // coalesced
}

// ---------------------------------------------------------------------------
// Kernel 1: GEMM G = F @ W^T (fp16 out). Clean.
// Grid (192,2): 64x64 tiles, 128 threads, 3 CTAs/SM. FFMA2 microtile 8x4.
// ---------------------------------------------------------------------------
__global__ void __launch_bounds__(128, 3)
gemm_G_kernel(const float* __restrict__ F, const float* __restrict__ W)
{
    extern __shared__ float sm[];
    float* Fst = sm;                 // 128 * 66  (Fst[k*66 + m])
    float* Wt  = sm + 128 * 66;      // 128 * 66  (Wt [k*66 + n])

    const int tid = threadIdx.x;
    const int bm  = blockIdx.x;
    const int bn  = blockIdx.y;

    const float* Fblk = F + (size_t)bm * 64 * DD;
    const float* Wblk = W + (size_t)bn * 64 * DD;

    #pragma unroll 8
    for (int idx = tid; idx < 64 * 128; idx += 128) {
        int r = idx >> 7, k = idx & 127;
        Fst[k * 66 + r] = Fblk[idx];
        Wt [k * 66 + r] = Wblk[idx];
    }
    __syncthreads();

    const int tx = tid & 15;   // cols 4*tx .. 4*tx+3
    const int ty = tid >> 4;   // rows 8*ty .. 8*ty+7

    ull acc[4][4];
    #pragma unroll
    for (int p = 0; p < 4; p++)
        #pragma unroll
        for (int c = 0; c < 4; c++)
            acc[p][c] = 0ULL;

    #pragma unroll 4
    for (int kk = 0; kk < 128; kk++) {
        const float* fr = &Fst[kk * 66 + 8 * ty];
        ull a2[4];
        #pragma unroll
        for (int p = 0; p < 4; p++)
            a2[p] = *reinterpret_cast<const ull*>(&fr[2 * p]);

        float2 b01 = *reinterpret_cast<const float2*>(&Wt[kk * 66 + 4 * tx]);
        float2 b23 = *reinterpret_cast<const float2*>(&Wt[kk * 66 + 4 * tx + 2]);
        ull bd[4];
        bd[0] = pack_dup(b01.x); bd[1] = pack_dup(b01.y);
        bd[2] = pack_dup(b23.x); bd[3] = pack_dup(b23.y);

        #pragma unroll
        for (int p = 0; p < 4; p++)
            #pragma unroll
            for (int c = 0; c < 4; c++)
                fma2(acc[p][c], a2[p], bd[c]);
    }

    float v[8][4];
    #pragma unroll
    for (int p = 0; p < 4; p++)
        #pragma unroll
        for (int c = 0; c < 4; c++) {
            float lo, hi;
            unpack2(lo, hi, acc[p][c]);
            v[2 * p][c]     = lo;
            v[2 * p + 1][c] = hi;
        }

    const int gm0 = bm * 64 + 8 * ty;
    const int gn0 = bn * 64 + 4 * tx;
    #pragma unroll
    for (int r = 0; r < 8; r++) {
        __half2 h01 = __floats2half2_rn(v[r][0], v[r][1]);
        __half2 h23 = __floats2half2_rn(v[r][2], v[r][3]);
        uint2 st;
        st.x = *reinterpret_cast<unsigned*>(&h01);
        st.y = *reinterpret_cast<unsigned*>(&h23);
        *reinterpret_cast<uint2*>(&g_Gh[(size_t)(gm0 + r) * DD + gn0]) = st;
    }
}

// ---------------------------------------------------------------------------
// Kernel 2: out[b][d] = relu( sum_k w[b][k] * G[nb[b][k]][d] + bias[d] )
// 256 thr = 16 nodes/block; warp handles 2 nodes (lanes 0-15 / 16-31),
// lane owns 8 fp16 cols (one LDG.128 per k). w precomputed (coalesced).
// Accumulate in packed f32x2 (4 fma2 per uint4 instead of 8 FFMA).
// ---------------------------------------------------------------------------
__global__ void __launch_bounds__(256)
gather_kernel(const int* __restrict__ neighbors,
              const float* __restrict__ b_lin,
              float* __restrict__ out)
{
    __shared__ int   nb_s[16][KK];
    __shared__ float w_s [16][KK];

    const int tid = threadIdx.x;
    const int b0  = blockIdx.x * 16;

    #pragma unroll
    for (int i = 0; i < 2; i++) {
        const int e  = tid + i * 256;
        const int ln = e >> 5;
        const int k  = e & 31;
        const int gi = (b0 + ln) * KK + k;
        nb_s[ln][k] = neighbors[gi];
        w_s [ln][k] = g_w[gi];
    }
    __syncthreads();

    const int lane = tid & 31;
    const int ln2  = ((tid >> 5) << 1) | (lane >> 4);  // local node 0..15
    const int col  = (lane & 15) * 8;                  // 8 cols per lane
    const int b    = b0 + ln2;

    ull acc[4];                                        // 8 fp32 accumulators
    #pragma unroll
    for (int i = 0; i < 4; i++) acc[i] = 0ULL;

    #pragma unroll
    for (int kb = 0; kb < KK; kb += 4) {
        uint4 g[4];
        float wv[4];
        #pragma unroll
        for (int u = 0; u < 4; u++) {
            const int nb = nb_s[ln2][kb + u];
            wv[u] = w_s[ln2][kb + u];
            g[u]  = __ldg(reinterpret_cast<const uint4*>(
                              &g_Gh[(size_t)nb * DD + col]));
        }
        #pragma unroll
        for (int u = 0; u < 4; u++) {
            const ull wd = pack_dup(wv[u]);
            float2 f0 = __half22float2(*reinterpret_cast<__half2*>(&g[u].x));
            float2 f1 = __half22float2(*reinterpret_cast<__half2*>(&g[u].y));
            float2 f2 = __half22float2(*reinterpret_cast<__half2*>(&g[u].z));
            float2 f3 = __half22float2(*reinterpret_cast<__half2*>(&g[u].w));
            fma2(acc[0], wd, *reinterpret_cast<ull*>(&f0));
            fma2(acc[1], wd, *reinterpret_cast<ull*>(&f1));
            fma2(acc[2], wd, *reinterpret_cast<ull*>(&f2));
            fma2(acc[3], wd, *reinterpret_cast<ull*>(&f3));
        }
    }

    float a[8];
    #pragma unroll
    for (int i = 0; i < 4; i++) unpack2(a[2 * i], a[2 * i + 1], acc[i]);

    const float4 bias0 = __ldg(reinterpret_cast<const float4*>(&b_lin[col]));
    const float4 bias1 = __ldg(reinterpret_cast<const float4*>(&b_lin[col + 4]));
    float4 o0, o1;
    o0.x = fmaxf(a[0] + bias0.x, 0.f);
    o0.y = fmaxf(a[1] + bias0.y, 0.f);
    o0.z = fmaxf(a[2] + bias0.z, 0.f);
    o0.w = fmaxf(a[3] + bias0.w, 0.f);
    o1.x = fmaxf(a[4] + bias1.x, 0.f);
    o1.y = fmaxf(a[5] + bias1.y, 0.f);
    o1.z = fmaxf(a[6] + bias1.z, 0.f);
    o1.w = fmaxf(a[7] + bias1.w, 0.f);
    float* op = &out[(size_t)b * DD + col];
    *reinterpret_cast<float4*>(op)     = o0;
    *reinterpret_cast<float4*>(op + 4) = o1;
}

// ---------------------------------------------------------------------------
// Launch. Inputs: nodes(i32 N), neighbors(i32 N*K), raw_features(f32 N*128),
//                 reweighted(f32 N*N), W_lin(f32 128*128), b_lin(f32 128)
// ---------------------------------------------------------------------------
extern "C" void kernel_launch(void* const* d_in, const int* in_sizes, int n_in,
                              void* d_out, int out_size)
{
    const int*   nodes      = (const int*)  d_in[0];
    const int*   neighbors  = (const int*)  d_in[1];
    const float* raw_feats  = (const float*)d_in[2];
    const float* reweighted = (const float*)d_in[3];
    const float* W_lin      = (const float*)d_in[4];
    const float* b_lin      = (const float*)d_in[5];
    float*       out        = (float*)d_out;

    const int smem = 2 * 128 * 66 * (int)sizeof(float);  // 67584 B
    static bool attr_set = false;
    if (!attr_set) {
        cudaFuncSetAttribute(gemm_G_kernel,
                             cudaFuncAttributeMaxDynamicSharedMemorySize, smem);
        attr_set = true;
    }

    wprep_kernel<<<NN * KK / 256, 256>>>(nodes, neighbors, reweighted);
    dim3 ggrid(NN / 64, DD / 64);
    gemm_G_kernel<<<ggrid, 128, smem>>>(raw_feats, W_lin);
    gather_kernel<<<NN / 16, 256>>>(neighbors, b_lin, out);
}